// round 8
// baseline (speedup 1.0000x reference)
#include <cuda_runtime.h>

// Loss_46883863003176: out = sum((pred - tgt)^2) / S / B
// pred, tgt: (4096, 2047, 2) float32, contiguous. Pure HBM-bound reduction.
//
// Block-CONTIGUOUS partitioning: 1024 blocks x 4096 float4 each (exact).
// Each unroll-4 batch reads contiguous 4KB stripes -> maximal DRAM row
// locality, 2 live pages per warp instead of 8. Unchanged R7 epilogue:
// pre-scaled atomicAdd into a device accumulator; last-arriving block
// (wraparound counter, self-resetting across graph replays) publishes to
// d_out and resets. Single launch, no memset, no allocations.

#define BLOCK_THREADS 256
#define NUM_BLOCKS    1024
#define CHUNK         4096        // float4 per block; NUM_BLOCKS*CHUNK >= n_vec4

__device__ float        g_accum   = 0.0f;  // running sum (reset by winner each launch)
__device__ unsigned int g_arrival = 0;     // wraps to 0 every NUM_BLOCKS arrivals

__global__ void __launch_bounds__(BLOCK_THREADS)
mse_fused_kernel(const float4* __restrict__ pred,
                 const float4* __restrict__ tgt,
                 float* __restrict__ out,
                 int n_vec4,          // number of float4 elements (multiple of 256)
                 float inv_norm)      // 1 / (S * B)
{
    const int tid   = threadIdx.x;
    const int start = blockIdx.x * CHUNK;
    const int end   = min(start + CHUNK, n_vec4);

    float acc = 0.0f;

    // Unroll-by-4 over the block's contiguous chunk: 8 independent LDG.128
    // in flight per thread, all four 4KB stripes contiguous.
    int i = start + tid;
    for (; i + 3 * BLOCK_THREADS < end; i += 4 * BLOCK_THREADS) {
        float4 p0 = __ldcs(&pred[i]);
        float4 p1 = __ldcs(&pred[i +     BLOCK_THREADS]);
        float4 p2 = __ldcs(&pred[i + 2 * BLOCK_THREADS]);
        float4 p3 = __ldcs(&pred[i + 3 * BLOCK_THREADS]);
        float4 t0 = __ldcs(&tgt[i]);
        float4 t1 = __ldcs(&tgt[i +     BLOCK_THREADS]);
        float4 t2 = __ldcs(&tgt[i + 2 * BLOCK_THREADS]);
        float4 t3 = __ldcs(&tgt[i + 3 * BLOCK_THREADS]);

        float d;
        d = p0.x - t0.x; acc = fmaf(d, d, acc);
        d = p0.y - t0.y; acc = fmaf(d, d, acc);
        d = p0.z - t0.z; acc = fmaf(d, d, acc);
        d = p0.w - t0.w; acc = fmaf(d, d, acc);
        d = p1.x - t1.x; acc = fmaf(d, d, acc);
        d = p1.y - t1.y; acc = fmaf(d, d, acc);
        d = p1.z - t1.z; acc = fmaf(d, d, acc);
        d = p1.w - t1.w; acc = fmaf(d, d, acc);
        d = p2.x - t2.x; acc = fmaf(d, d, acc);
        d = p2.y - t2.y; acc = fmaf(d, d, acc);
        d = p2.z - t2.z; acc = fmaf(d, d, acc);
        d = p2.w - t2.w; acc = fmaf(d, d, acc);
        d = p3.x - t3.x; acc = fmaf(d, d, acc);
        d = p3.y - t3.y; acc = fmaf(d, d, acc);
        d = p3.z - t3.z; acc = fmaf(d, d, acc);
        d = p3.w - t3.w; acc = fmaf(d, d, acc);
    }
    // Tail: uniform across threads (n_vec4 and CHUNK are multiples of 256).
    for (; i < end; i += BLOCK_THREADS) {
        float4 p = __ldcs(&pred[i]);
        float4 t = __ldcs(&tgt[i]);
        float d;
        d = p.x - t.x; acc = fmaf(d, d, acc);
        d = p.y - t.y; acc = fmaf(d, d, acc);
        d = p.z - t.z; acc = fmaf(d, d, acc);
        d = p.w - t.w; acc = fmaf(d, d, acc);
    }

    // Warp reduce
    #pragma unroll
    for (int off = 16; off > 0; off >>= 1)
        acc += __shfl_xor_sync(0xFFFFFFFFu, acc, off);

    // Block reduce via shared
    __shared__ float warp_sums[BLOCK_THREADS / 32];
    __shared__ bool  is_last;
    const int lane = tid & 31;
    const int wid  = tid >> 5;
    if (lane == 0) warp_sums[wid] = acc;
    __syncthreads();

    if (tid == 0) {
        float v = 0.0f;
        #pragma unroll
        for (int w = 0; w < BLOCK_THREADS / 32; w++)
            v += warp_sums[w];

        // Pre-scale so the final value needs no further math.
        atomicAdd(&g_accum, v * inv_norm);
        __threadfence();   // order the add before the arrival increment
        // atomicInc wraps to 0 at NUM_BLOCKS-1 -> self-resets each launch,
        // keeping graph replays deterministic.
        unsigned int prev = atomicInc(&g_arrival, NUM_BLOCKS - 1);
        is_last = (prev == NUM_BLOCKS - 1);
    }
    __syncthreads();

    // Last block: publish result, reset accumulator for the next replay.
    if (is_last && tid == 0) {
        float total = atomicAdd(&g_accum, 0.0f);   // atomic read
        out[0] = total;                             // overwrite poisoned d_out
        __threadfence();
        atomicExch(&g_accum, 0.0f);                 // reset for next launch
    }
}

extern "C" void kernel_launch(void* const* d_in, const int* in_sizes, int n_in,
                              void* d_out, int out_size)
{
    const float* pred = (const float*)d_in[0];
    const float* tgt  = (const float*)d_in[1];
    float* out = (float*)d_out;

    const long long total = (long long)in_sizes[0];   // B * S * 2 = 16,769,024
    const int n_vec4 = (int)(total / 4);              // 4,192,256 (mult of 256)
    // normalizer: S * B = total / 2
    const float inv_norm = 2.0f / (float)total;

    mse_fused_kernel<<<NUM_BLOCKS, BLOCK_THREADS>>>(
        (const float4*)pred, (const float4*)tgt, out, n_vec4, inv_norm);
}